// round 14
// baseline (speedup 1.0000x reference)
#include <cuda_runtime.h>
#include <cstdint>

#define N_TOK 12288
#define DHEAD 128
#define NUMB  32
#define BM 64
#define BN 64
#define KSPLIT 128
#define MAXPARTS 6
#define NTHREADS 256
#define NWORKERS 296

__device__ int  g_seg_start[NUMB + 1];
__device__ int  g_ctr;
__device__ float g_pO[MAXPARTS][N_TOK][DHEAD];  // unnormalized partial O
__device__ float g_pl[MAXPARTS][N_TOK];          // partial row sums

// ---------------------------------------------------------------------------
// Prep (multi-block, one thread per token): boundary-detect segment starts.
// ---------------------------------------------------------------------------
__global__ void prep_kernel(const int* __restrict__ bseg) {
    int i = blockIdx.x * blockDim.x + threadIdx.x;
    if (i == 0) {
        g_ctr = 0;
        int c = bseg[0];
        for (int b = 0; b <= c; b++) g_seg_start[b] = 0;
        int last = bseg[N_TOK - 1];
        for (int b = last + 1; b <= NUMB; b++) g_seg_start[b] = N_TOK;
    } else if (i < N_TOK) {
        int a = bseg[i - 1], c = bseg[i];
        for (int b = a + 1; b <= c; b++) g_seg_start[b] = i;
    }
}

// ---------------------------------------------------------------------------
// PTX helpers
// ---------------------------------------------------------------------------
__device__ __forceinline__ void cp16(uint32_t dst, const void* src) {
    asm volatile("cp.async.cg.shared.global [%0], [%1], 16;" :: "r"(dst), "l"(src));
}
__device__ __forceinline__ void cp_commit() {
    asm volatile("cp.async.commit_group;" ::: "memory");
}
template <int NG> __device__ __forceinline__ void cp_wait() {
    asm volatile("cp.async.wait_group %0;" :: "n"(NG) : "memory");
}
__device__ __forceinline__ void fma2(unsigned long long& d,
                                     const unsigned long long a,
                                     const unsigned long long b) {
    asm volatile("fma.rn.f32x2 %0, %1, %2, %0;" : "+l"(d) : "l"(a), "l"(b));
}
__device__ __forceinline__ unsigned long long dup2(float x) {
    unsigned long long d;
    asm("mov.b64 %0, {%1, %1};" : "=l"(d) : "f"(x));
    return d;
}

// ---------------------------------------------------------------------------
// Main kernel (R9 champion core). 256 threads = 8 warps; warp wy owns rows
// wy*8..+7 of the item; lane tx owns score cols {2tx,2tx+1}, out cols 4tx..+3.
// Smem (112KB, 2 CTAs/SM): Q linear, A/B swizzled double-buffer, P (e0,e1).
// Pipeline: V(t)->B overlaps QK(t) on A; K(t+1)->A overlaps PV(t) on B.
// Dynamic atomic work queue; item mapping from per-CTA s_iofs prefix.
// ---------------------------------------------------------------------------
__global__ __launch_bounds__(NTHREADS, 2)
void attn_kernel(const float* __restrict__ Q, const float* __restrict__ K,
                 const float* __restrict__ V, const int* __restrict__ bseg) {
    extern __shared__ float smf[];
    float* Qs = smf;            // [64][128] 32KB linear
    float* Ab = smf + 8192;     // [64][128] 32KB swizzled (K tile)
    float* Bb = smf + 16384;    // [64][128] 32KB swizzled (V tile)
    float* Ps = smf + 24576;    // [64][64]  16KB (e0,e1) pairs
    __shared__ int s_seg[NUMB + 1];
    __shared__ int s_iofs[NUMB + 1];
    __shared__ int s_work;

    const int tid = threadIdx.x;
    const int tx  = tid & 31;
    const int wy  = tid >> 5;                 // 0..7
    const uint32_t sm_u = (uint32_t)__cvta_generic_to_shared(smf);
    const uint32_t qs_u = sm_u;
    const uint32_t a_u  = sm_u + 8192u * 4u;
    const uint32_t b_u  = sm_u + 16384u * 4u;
    const float isd = 0.0883883476483184f;    // 1/sqrt(128)
    const int ksw = tx & 7;                   // swizzle of rows 2tx,2tx+1

    // per-CTA: load seg table, build item-offset prefix
    if (tid <= NUMB) s_seg[tid] = g_seg_start[tid];
    __syncthreads();
    if (tid == 0) {
        int run = 0;
        for (int b2 = 0; b2 < NUMB; b2++) {
            s_iofs[b2] = run;
            int rows = s_seg[b2 + 1] - s_seg[b2];
            run += ((rows + BM - 1) / BM) * ((rows + KSPLIT - 1) / KSPLIT);
        }
        s_iofs[NUMB] = run;
    }
    __syncthreads();
    const int nitems = s_iofs[NUMB];

    while (true) {
        __syncthreads();                      // prev item's smem reads done
        if (tid == 0) s_work = atomicAdd(&g_ctr, 1);
        __syncthreads();
        const int w = s_work;
        if (w >= nitems) break;

        // map w -> (r0, nrows, klo, khi, part)
        int b2 = 0;
        while (w >= s_iofs[b2 + 1]) b2++;
        int rel = w - s_iofs[b2];
        int lo = s_seg[b2], hi = s_seg[b2 + 1];
        int nkp = (hi - lo + KSPLIT - 1) / KSPLIT;
        int rt  = rel / nkp;
        const int part  = rel - rt * nkp;
        const int r0    = lo + rt * BM;
        const int nrows = min(BM, hi - r0);
        const int klo   = lo + part * KSPLIT;
        const int khi   = min(klo + KSPLIT, hi);

        // Issue Q tile + first K tile (one async group)
        #pragma unroll
        for (int t = 0; t < 8; t++) {
            int idx = tid + t * NTHREADS;
            int r = idx >> 5, c4 = idx & 31;
            int gq = r0 + min(r, nrows - 1);
            cp16(qs_u + (r << 9) + (c4 << 4), Q + (size_t)gq * DHEAD + c4 * 4);
            int gk = klo + r; if (gk >= khi) gk = khi - 1;
            int off = (r << 9) + ((c4 ^ ((r >> 1) & 7)) << 4);
            cp16(a_u + off, K + (size_t)gk * DHEAD + c4 * 4);
        }
        cp_commit();

        unsigned long long o2[8][2];
        float lsum[8];
        #pragma unroll
        for (int i = 0; i < 8; i++) { o2[i][0] = 0ULL; o2[i][1] = 0ULL; lsum[i] = 0.f; }

        for (int kt = klo; kt < khi; kt += BN) {
            cp_wait<0>();                     // K(t) (and Q on first iter) done
            __syncthreads();                  // visible; B free (prev PV done)

            // Issue V(t) -> B (overlaps QK below)
            #pragma unroll
            for (int t = 0; t < 8; t++) {
                int idx = tid + t * NTHREADS;
                int r = idx >> 5, c4 = idx & 31;
                int gr = kt + r; if (gr >= khi) gr = khi - 1;
                int off = (r << 9) + ((c4 ^ ((r >> 1) & 7)) << 4);
                cp16(b_u + off, V + (size_t)gr * DHEAD + c4 * 4);
            }
            cp_commit();

            // ---- QK: 8 rows x 2 cols per lane, from A ----
            const float* kp0 = Ab + (2 * tx) * 128;
            const float* kp1 = kp0 + 128;
            const float* qp  = Qs + (wy * 8) * 128;
            unsigned long long s2[8][2];
            #pragma unroll
            for (int i = 0; i < 8; i++) { s2[i][0] = 0ULL; s2[i][1] = 0ULL; }

            #pragma unroll 4
            for (int c = 0; c < 32; c++) {
                int kph = (c ^ ksw) << 2;
                ulonglong2 ka = *(const ulonglong2*)(kp0 + kph);
                ulonglong2 kb = *(const ulonglong2*)(kp1 + kph);
                const float* qc = qp + (c << 2);
                #pragma unroll
                for (int i = 0; i < 8; i++) {
                    ulonglong2 qa = *(const ulonglong2*)(qc + i * 128);
                    fma2(s2[i][0], qa.x, ka.x);
                    fma2(s2[i][0], qa.y, ka.y);
                    fma2(s2[i][1], qa.x, kb.x);
                    fma2(s2[i][1], qa.y, kb.y);
                }
            }

            // ---- masked exp, P store (e0,e1) once ----
            const int col0 = kt + 2 * tx;
            #pragma unroll
            for (int i = 0; i < 8; i++) {
                unsigned long long v0 = s2[i][0], v1 = s2[i][1];
                float sv0 = (__uint_as_float((unsigned)v0) +
                             __uint_as_float((unsigned)(v0 >> 32))) * isd;
                float sv1 = (__uint_as_float((unsigned)v1) +
                             __uint_as_float((unsigned)(v1 >> 32))) * isd;
                float e0 = (col0     < khi) ? __expf(sv0) : 0.f;
                float e1 = (col0 + 1 < khi) ? __expf(sv1) : 0.f;
                lsum[i] += e0 + e1;
                float2 ev; ev.x = e0; ev.y = e1;
                *(float2*)(Ps + (wy * 8 + i) * 64 + tx * 2) = ev;
            }
            __syncthreads();                  // P visible; all A reads done

            // Issue K(t+1) -> A (overlaps PV below)
            const bool hasnext = (kt + BN) < khi;
            if (hasnext) {
                #pragma unroll
                for (int t = 0; t < 8; t++) {
                    int idx = tid + t * NTHREADS;
                    int r = idx >> 5, c4 = idx & 31;
                    int gr = kt + BN + r; if (gr >= khi) gr = khi - 1;
                    int off = (r << 9) + ((c4 ^ ((r >> 1) & 7)) << 4);
                    cp16(a_u + off, K + (size_t)gr * DHEAD + c4 * 4);
                }
                cp_commit();
                cp_wait<1>();                 // V(t) done; K(t+1) in flight
            } else {
                cp_wait<0>();                 // V(t) done
            }
            __syncthreads();                  // V visible

            // ---- PV from B; P pairs duplicated in registers ----
            const float* pp = Ps + (wy * 8) * 64;
            #pragma unroll 4
            for (int c2 = 0; c2 < 32; c2++) {
                int ph = (tx ^ (c2 & 7)) << 2;
                const float* vrow = Bb + (2 * c2) * 128 + ph;
                ulonglong2 vv0 = *(const ulonglong2*)(vrow);        // row 2c2
                ulonglong2 vv1 = *(const ulonglong2*)(vrow + 128);  // row 2c2+1
                #pragma unroll
                for (int i = 0; i < 8; i++) {
                    float2 pu = *(const float2*)(pp + i * 64 + c2 * 2);
                    unsigned long long d0 = dup2(pu.x);
                    unsigned long long d1 = dup2(pu.y);
                    fma2(o2[i][0], d0, vv0.x);
                    fma2(o2[i][1], d0, vv0.y);
                    fma2(o2[i][0], d1, vv1.x);
                    fma2(o2[i][1], d1, vv1.y);
                }
            }
        }

        // ---- epilogue: reduce l, store UNNORMALIZED partials ----
        #pragma unroll
        for (int i = 0; i < 8; i++) {
            float l = lsum[i];
            #pragma unroll
            for (int o = 16; o >= 1; o >>= 1)
                l += __shfl_xor_sync(0xffffffffu, l, o);
            int row = wy * 8 + i;
            if (row < nrows) {
                int gr = r0 + row;
                unsigned long long a = o2[i][0], bb = o2[i][1];
                float4 r4;
                r4.x = __uint_as_float((unsigned)a);
                r4.y = __uint_as_float((unsigned)(a >> 32));
                r4.z = __uint_as_float((unsigned)bb);
                r4.w = __uint_as_float((unsigned)(bb >> 32));
                *(float4*)&g_pO[part][gr][tx * 4] = r4;
                if (tx == 0) g_pl[part][gr] = l;
            }
        }
    }
}

// ---------------------------------------------------------------------------
// Combine: out[r] = sum_p pO[p][r] / sum_p pl[p][r]
// ---------------------------------------------------------------------------
__global__ void combine_kernel(const int* __restrict__ bseg,
                               float* __restrict__ out) {
    int idx = blockIdx.x * blockDim.x + threadIdx.x;   // 0 .. N_TOK*32-1
    int r  = idx >> 5;
    int c4 = idx & 31;
    int b  = bseg[r];
    int span = g_seg_start[b + 1] - g_seg_start[b];
    int np = (span + KSPLIT - 1) / KSPLIT;
    float4 a = *(const float4*)&g_pO[0][r][c4 * 4];
    float  l = g_pl[0][r];
    for (int p = 1; p < np; p++) {
        float4 t = *(const float4*)&g_pO[p][r][c4 * 4];
        a.x += t.x; a.y += t.y; a.z += t.z; a.w += t.w;
        l += g_pl[p][r];
    }
    float inv = 1.0f / l;   // EPS negligible (validated R2-R11)
    a.x *= inv; a.y *= inv; a.z *= inv; a.w *= inv;
    *(float4*)&out[(size_t)r * DHEAD + c4 * 4] = a;
}

// ---------------------------------------------------------------------------
extern "C" void kernel_launch(void* const* d_in, const int* in_sizes, int n_in,
                              void* d_out, int out_size) {
    const float* Q  = (const float*)d_in[0];
    const float* K  = (const float*)d_in[1];
    const float* V  = (const float*)d_in[2];
    const int* bseg = (const int*)d_in[n_in - 1];
    float* out      = (float*)d_out;

    const int smem_bytes = (8192 * 3 + 4096) * (int)sizeof(float);   // 112KB
    cudaFuncSetAttribute(attn_kernel, cudaFuncAttributeMaxDynamicSharedMemorySize,
                         smem_bytes);

    prep_kernel<<<N_TOK / 256, 256>>>(bseg);
    attn_kernel<<<NWORKERS, NTHREADS, smem_bytes>>>(Q, K, V, bseg);
    combine_kernel<<<N_TOK * 32 / 256, 256>>>(bseg, out);
}

// round 16
// speedup vs baseline: 1.8030x; 1.8030x over previous
#include <cuda_runtime.h>
#include <cuda_bf16.h>
#include <cstdint>

#define N_TOK 12288
#define DHEAD 128
#define NUMB  32
#define BM 64
#define BN 64
#define KSPLIT 128
#define MAXPARTS 6
#define NTHREADS 256
#define NWORKERS 296

// dynamic smem byte offsets (112KB total -> 2 CTAs/SM)
#define QH_O 0
#define KH_O 32768
#define VH_O 65536
#define PH_O 98304
#define HL_GAP 16384      // QL=QH+GAP, KL, VL
#define P_GAP  8192       // PL=PH+8192
#define SMEMB 114688

__device__ int   g_seg_start[NUMB + 1];
__device__ int   g_ctr;
__device__ float g_pO[MAXPARTS][N_TOK][DHEAD];
__device__ float g_pl[MAXPARTS][N_TOK];

// ---------------------------------------------------------------------------
__global__ void prep_kernel(const int* __restrict__ bseg) {
    int i = blockIdx.x * blockDim.x + threadIdx.x;
    if (i == 0) {
        g_ctr = 0;
        int c = bseg[0];
        for (int b = 0; b <= c; b++) g_seg_start[b] = 0;
        int last = bseg[N_TOK - 1];
        for (int b = last + 1; b <= NUMB; b++) g_seg_start[b] = N_TOK;
    } else if (i < N_TOK) {
        int a = bseg[i - 1], c = bseg[i];
        for (int b = a + 1; b <= c; b++) g_seg_start[b] = i;
    }
}

// ---------------------------------------------------------------------------
// helpers
// ---------------------------------------------------------------------------
__device__ __forceinline__ uint32_t packhl(float a, float b, uint32_t& lo) {
    __nv_bfloat16 ha = __float2bfloat16(a), hb = __float2bfloat16(b);
    __nv_bfloat16 la = __float2bfloat16(a - __bfloat162float(ha));
    __nv_bfloat16 lb = __float2bfloat16(b - __bfloat162float(hb));
    lo = (uint32_t)__bfloat16_as_ushort(la) | ((uint32_t)__bfloat16_as_ushort(lb) << 16);
    return (uint32_t)__bfloat16_as_ushort(ha) | ((uint32_t)__bfloat16_as_ushort(hb) << 16);
}
__device__ __forceinline__ void ldsm4(uint32_t* r, uint32_t a) {
    asm volatile("ldmatrix.sync.aligned.m8n8.x4.shared.b16 {%0,%1,%2,%3}, [%4];"
        : "=r"(r[0]), "=r"(r[1]), "=r"(r[2]), "=r"(r[3]) : "r"(a));
}
__device__ __forceinline__ void ldsm4t(uint32_t* r, uint32_t a) {
    asm volatile("ldmatrix.sync.aligned.m8n8.x4.trans.shared.b16 {%0,%1,%2,%3}, [%4];"
        : "=r"(r[0]), "=r"(r[1]), "=r"(r[2]), "=r"(r[3]) : "r"(a));
}
__device__ __forceinline__ void mmab(float* d, const uint32_t* a, uint32_t b0, uint32_t b1) {
    asm("mma.sync.aligned.m16n8k16.row.col.f32.bf16.bf16.f32 "
        "{%0,%1,%2,%3}, {%4,%5,%6,%7}, {%8,%9}, {%0,%1,%2,%3};"
        : "+f"(d[0]), "+f"(d[1]), "+f"(d[2]), "+f"(d[3])
        : "r"(a[0]), "r"(a[1]), "r"(a[2]), "r"(a[3]), "r"(b0), "r"(b1));
}
// load 64x128 f32 gmem tile (rows row0.., clamped to cap-1) -> bf16 hi/lo smem
// layout: row stride 256B, 16B chunk swizzle c^(r&7)
__device__ __forceinline__ void ldcv(const float* __restrict__ src, int row0, int cap,
                                     char* smc, int Ho, int tid) {
    #pragma unroll
    for (int t = 0; t < 8; t++) {
        int idx = tid + (t << 8);
        int r = idx >> 5, c4 = idx & 31;
        int gr = row0 + r; if (gr >= cap) gr = cap - 1;
        float4 v = *(const float4*)(src + (size_t)gr * DHEAD + (c4 << 2));
        uint32_t l0, l1;
        uint32_t h0 = packhl(v.x, v.y, l0);
        uint32_t h1 = packhl(v.z, v.w, l1);
        int byte = (r << 8) + ((((c4 >> 1) ^ (r & 7)) << 4) + ((c4 & 1) << 3));
        *(uint2*)(smc + Ho + byte)          = make_uint2(h0, h1);
        *(uint2*)(smc + Ho + HL_GAP + byte) = make_uint2(l0, l1);
    }
}

// ---------------------------------------------------------------------------
// HMMA attention. 8 warps: wr=wid&3 (16 rows), wc=wid>>2 (32 S-cols / 64 O-cols).
// QK: S(64x64) via m16n8k16 bf16 hi/lo (3 passes). PV: O(64x128) likewise,
// V read with ldmatrix.trans from natural [key][d] layout.
// ---------------------------------------------------------------------------
__global__ __launch_bounds__(NTHREADS, 2)
void attn_kernel(const float* __restrict__ Q, const float* __restrict__ K,
                 const float* __restrict__ V, const int* __restrict__ bseg) {
    extern __shared__ char smc[];
    __shared__ int s_seg[NUMB + 1], s_iofs[NUMB + 1], s_work;
    __shared__ float Lx[2][64];

    const int tid = threadIdx.x;
    const int lane = tid & 31, wid = tid >> 5;
    const int wr = wid & 3, wc = wid >> 2;
    const int g = lane >> 2, qx = lane & 3;
    const int arow = (lane & 7) + ((lane >> 3) & 1) * 8;
    const int asel = lane >> 4, lx7 = lane & 7;
    const uint32_t smu = (uint32_t)__cvta_generic_to_shared(smc);
    const float isd = 0.0883883476483184f;

    if (tid <= NUMB) s_seg[tid] = g_seg_start[tid];
    __syncthreads();
    if (tid == 0) {
        int run = 0;
        for (int b = 0; b < NUMB; b++) {
            s_iofs[b] = run;
            int rows = s_seg[b + 1] - s_seg[b];
            run += ((rows + BM - 1) / BM) * ((rows + KSPLIT - 1) / KSPLIT);
        }
        s_iofs[NUMB] = run;
    }
    __syncthreads();
    const int nitems = s_iofs[NUMB];

    // per-lane ldmatrix base addresses
    const uint32_t qbase = smu + QH_O + (uint32_t)(16 * wr + arow) * 256;
    const uint32_t kbase = smu + KH_O + (uint32_t)(32 * wc + arow) * 256;
    const uint32_t pbase = smu + PH_O + (uint32_t)(16 * wr + arow) * 128;

    while (true) {
        __syncthreads();
        if (tid == 0) s_work = atomicAdd(&g_ctr, 1);
        __syncthreads();
        const int w = s_work;
        if (w >= nitems) break;
        int b2 = 0; while (w >= s_iofs[b2 + 1]) b2++;
        int rel = w - s_iofs[b2];
        int lo = s_seg[b2], hi = s_seg[b2 + 1];
        int nkp = (hi - lo + KSPLIT - 1) / KSPLIT;
        int rt = rel / nkp;
        const int part = rel - rt * nkp;
        const int r0g = lo + rt * BM, nrows = min(BM, hi - r0g);
        const int klo = lo + part * KSPLIT, kend = min(klo + KSPLIT, hi);

        ldcv(Q, r0g, r0g + nrows, smc, QH_O, tid);     // Q -> QH/QL (sync below)

        float o[8][4];
        #pragma unroll
        for (int t = 0; t < 8; t++)
            { o[t][0] = 0.f; o[t][1] = 0.f; o[t][2] = 0.f; o[t][3] = 0.f; }
        float lsg0 = 0.f, lsg1 = 0.f;

        for (int kt = klo; kt < kend; kt += BN) {
            __syncthreads();                    // prev PV done; Q ready (1st iter)
            ldcv(K, kt, kend, smc, KH_O, tid);  // K(t)
            __syncthreads();

            // ---- QK: 4 n8-tiles x 8 k16-chunks x 3 passes ----
            float cs[4][4];
            #pragma unroll
            for (int t = 0; t < 4; t++)
                { cs[t][0] = 0.f; cs[t][1] = 0.f; cs[t][2] = 0.f; cs[t][3] = 0.f; }
            #pragma unroll
            for (int kc = 0; kc < 8; kc++) {
                uint32_t co = (uint32_t)(((2 * kc + asel) ^ lx7) << 4);
                uint32_t ah[4], al[4], b0h[4], b1h[4], b0l[4], b1l[4];
                ldsm4(ah, qbase + co);
                ldsm4(al, qbase + HL_GAP + co);
                ldsm4(b0h, kbase + co);
                ldsm4(b1h, kbase + 4096 + co);
                ldsm4(b0l, kbase + HL_GAP + co);
                ldsm4(b1l, kbase + HL_GAP + 4096 + co);
                mmab(cs[0], ah, b0h[0], b0h[2]);
                mmab(cs[0], ah, b0l[0], b0l[2]);
                mmab(cs[0], al, b0h[0], b0h[2]);
                mmab(cs[1], ah, b0h[1], b0h[3]);
                mmab(cs[1], ah, b0l[1], b0l[3]);
                mmab(cs[1], al, b0h[1], b0h[3]);
                mmab(cs[2], ah, b1h[0], b1h[2]);
                mmab(cs[2], ah, b1l[0], b1l[2]);
                mmab(cs[2], al, b1h[0], b1h[2]);
                mmab(cs[3], ah, b1h[1], b1h[3]);
                mmab(cs[3], ah, b1l[1], b1l[3]);
                mmab(cs[3], al, b1h[1], b1h[3]);
            }

            // ---- exp + mask + P store (bf16 hi/lo) ----
            #pragma unroll
            for (int t = 0; t < 4; t++) {
                int nb = 32 * wc + 8 * t;
                int col0 = kt + nb + 2 * qx;
                float e0 = (col0     < kend) ? __expf(cs[t][0] * isd) : 0.f;
                float e1 = (col0 + 1 < kend) ? __expf(cs[t][1] * isd) : 0.f;
                float e2 = (col0     < kend) ? __expf(cs[t][2] * isd) : 0.f;
                float e3 = (col0 + 1 < kend) ? __expf(cs[t][3] * isd) : 0.f;
                lsg0 += e0 + e1; lsg1 += e2 + e3;
                int tc = nb >> 3;
                int rA = 16 * wr + g, rB = rA + 8;
                uint32_t pl0, pl1;
                uint32_t ph0 = packhl(e0, e1, pl0);
                uint32_t ph1 = packhl(e2, e3, pl1);
                uint32_t offA = (uint32_t)(rA * 128 + ((tc ^ (rA & 7)) << 4) + 4 * qx);
                uint32_t offB = (uint32_t)(rB * 128 + ((tc ^ (rB & 7)) << 4) + 4 * qx);
                *(uint32_t*)(smc + PH_O + offA) = ph0;
                *(uint32_t*)(smc + PH_O + P_GAP + offA) = pl0;
                *(uint32_t*)(smc + PH_O + offB) = ph1;
                *(uint32_t*)(smc + PH_O + P_GAP + offB) = pl1;
            }
            __syncthreads();                    // P visible; K reads done
            ldcv(V, kt, kend, smc, VH_O, tid);  // V(t)
            __syncthreads();

            // ---- PV: 8 n8-tiles x 4 k16-chunks x 3 passes ----
            #pragma unroll
            for (int kc = 0; kc < 4; kc++) {
                uint32_t co = (uint32_t)(((2 * kc + asel) ^ lx7) << 4);
                uint32_t pah[4], pal[4];
                ldsm4(pah, pbase + co);
                ldsm4(pal, pbase + P_GAP + co);
                uint32_t vb = smu + VH_O + (uint32_t)(16 * kc + arow) * 256;
                #pragma unroll
                for (int i = 0; i < 4; i++) {
                    uint32_t vo = (uint32_t)(((8 * wc + 2 * i + asel) ^ lx7) << 4);
                    uint32_t vh[4], vl[4];
                    ldsm4t(vh, vb + vo);
                    ldsm4t(vl, vb + HL_GAP + vo);
                    mmab(o[2 * i], pah, vh[0], vh[1]);
                    mmab(o[2 * i], pah, vl[0], vl[1]);
                    mmab(o[2 * i], pal, vh[0], vh[1]);
                    mmab(o[2 * i + 1], pah, vh[2], vh[3]);
                    mmab(o[2 * i + 1], pah, vl[2], vl[3]);
                    mmab(o[2 * i + 1], pal, vh[2], vh[3]);
                }
            }
        }

        // ---- epilogue ----
        float s0 = lsg0, s1 = lsg1;
        s0 += __shfl_xor_sync(0xffffffffu, s0, 1);
        s0 += __shfl_xor_sync(0xffffffffu, s0, 2);
        s1 += __shfl_xor_sync(0xffffffffu, s1, 1);
        s1 += __shfl_xor_sync(0xffffffffu, s1, 2);
        if (qx == 0) { Lx[wc][16 * wr + g] = s0; Lx[wc][16 * wr + g + 8] = s1; }
        int rA = 16 * wr + g, rB = rA + 8;
        if (rA < nrows) {
            float* dst = &g_pO[part][r0g + rA][64 * wc + 2 * qx];
            #pragma unroll
            for (int t = 0; t < 8; t++)
                *(float2*)(dst + 8 * t) = make_float2(o[t][0], o[t][1]);
        }
        if (rB < nrows) {
            float* dst = &g_pO[part][r0g + rB][64 * wc + 2 * qx];
            #pragma unroll
            for (int t = 0; t < 8; t++)
                *(float2*)(dst + 8 * t) = make_float2(o[t][2], o[t][3]);
        }
        __syncthreads();
        if (tid < 64 && tid < nrows)
            g_pl[part][r0g + tid] = Lx[0][tid] + Lx[1][tid];
    }
}

// ---------------------------------------------------------------------------
__global__ void combine_kernel(const int* __restrict__ bseg,
                               float* __restrict__ out) {
    int idx = blockIdx.x * blockDim.x + threadIdx.x;
    int r = idx >> 5, c4 = idx & 31;
    int b = bseg[r];
    int span = g_seg_start[b + 1] - g_seg_start[b];
    int np = (span + KSPLIT - 1) / KSPLIT;
    float4 a = *(const float4*)&g_pO[0][r][c4 * 4];
    float l = g_pl[0][r];
    for (int p = 1; p < np; p++) {
        float4 t = *(const float4*)&g_pO[p][r][c4 * 4];
        a.x += t.x; a.y += t.y; a.z += t.z; a.w += t.w;
        l += g_pl[p][r];
    }
    float inv = 1.0f / l;   // EPS negligible (validated R2-R14)
    a.x *= inv; a.y *= inv; a.z *= inv; a.w *= inv;
    *(float4*)&out[(size_t)r * DHEAD + c4 * 4] = a;
}

// ---------------------------------------------------------------------------
extern "C" void kernel_launch(void* const* d_in, const int* in_sizes, int n_in,
                              void* d_out, int out_size) {
    const float* Q  = (const float*)d_in[0];
    const float* K  = (const float*)d_in[1];
    const float* V  = (const float*)d_in[2];
    const int* bseg = (const int*)d_in[n_in - 1];
    float* out      = (float*)d_out;

    cudaFuncSetAttribute(attn_kernel, cudaFuncAttributeMaxDynamicSharedMemorySize,
                         SMEMB);
    prep_kernel<<<N_TOK / 256, 256>>>(bseg);
    attn_kernel<<<NWORKERS, NTHREADS, SMEMB>>>(Q, K, V, bseg);
    combine_kernel<<<N_TOK * 32 / 256, 256>>>(bseg, out);
}